// round 1
// baseline (speedup 1.0000x reference)
#include <cuda_runtime.h>
#include <cstdint>
#include <cstddef>

// AspectAttention fused kernel, round 1: tf32 mma.sync GEMM + fused tanh/softmax/weighted-sum.
// Grid: 2048 CTAs (2 batches each), 512 threads (16 warps, 4x4 warp grid, 32x64 warp tiles).

#define KC       64     // k-chunk rows of W staged in smem
#define WSTRIDE  264    // padded floats per W smem row (264 % 32 == 8 -> conflict-free B frags)
#define THREADS  512

__device__ __forceinline__ uint32_t f2tf(float x) {
    uint32_t r;
    asm("cvt.rna.tf32.f32 %0, %1;" : "=r"(r) : "f"(x));
    return r;
}

__device__ __forceinline__ void mma_tf32(float (&c)[4],
                                         uint32_t a0, uint32_t a1, uint32_t a2, uint32_t a3,
                                         uint32_t b0, uint32_t b1) {
    asm volatile(
        "mma.sync.aligned.m16n8k8.row.col.f32.tf32.tf32.f32 "
        "{%0,%1,%2,%3},{%4,%5,%6,%7},{%8,%9},{%0,%1,%2,%3};"
        : "+f"(c[0]), "+f"(c[1]), "+f"(c[2]), "+f"(c[3])
        : "r"(a0), "r"(a1), "r"(a2), "r"(a3), "r"(b0), "r"(b1));
}

__device__ __forceinline__ void cp_async16(void* smem_dst, const void* gsrc) {
    uint32_t sa = (uint32_t)__cvta_generic_to_shared(smem_dst);
    asm volatile("cp.async.cg.shared.global [%0], [%1], 16;" :: "r"(sa), "l"(gsrc));
}

// smem layout (floats):
//   wbuf   : 2 * KC * WSTRIDE = 33792
//   colpart: 2 * 512          = 1024   (per (wm&1), [batch*256 + col])
//   inv    : 512                      (1/colsum per [batch*256 + col])
//   rowpart: 4 * 128          = 512   (per warp_n, [row])
#define SMEM_FLOATS (2*KC*WSTRIDE + 1024 + 512 + 512)

__global__ __launch_bounds__(THREADS, 1)
void aspect_attention_kernel(const float* __restrict__ h,
                             const float* __restrict__ W,
                             const float* __restrict__ bias,
                             float* __restrict__ out) {
    extern __shared__ float smem[];
    float* wbuf    = smem;                      // [2][KC][WSTRIDE]
    float* colpart = smem + 2 * KC * WSTRIDE;   // [2][512]
    float* inv     = colpart + 1024;            // [512]
    float* rowpart = inv + 512;                 // [4][128]

    const int tid  = threadIdx.x;
    const int wid  = tid >> 5;
    const int lane = tid & 31;
    const int g    = lane >> 2;   // 0..7
    const int tig  = lane & 3;    // 0..3
    const int wm   = wid & 3;     // warp_m: rows wm*32 .. wm*32+31
    const int wn   = wid >> 2;    // warp_n: cols wn*64 .. wn*64+63
    const int batch = wm >> 1;    // rows 0-63 -> batch 0, rows 64-127 -> batch 1

    const float* hb = h + (size_t)blockIdx.x * (128 * 256);

    float acc[2][8][4];
    #pragma unroll
    for (int mf = 0; mf < 2; ++mf)
        #pragma unroll
        for (int nt = 0; nt < 8; ++nt)
            #pragma unroll
            for (int i = 0; i < 4; ++i)
                acc[mf][nt][i] = 0.0f;

    // ---------------- GEMM: S = H @ W, k-chunked, double-buffered W via cp.async ----
    // issue chunk 0
    {
        const float* src = W;  // chunk 0
        #pragma unroll
        for (int it = 0; it < 8; ++it) {
            int idx = it * THREADS + tid;
            int row = idx >> 6, q = idx & 63;
            cp_async16(wbuf + row * WSTRIDE + q * 4, src + row * 256 + q * 4);
        }
        asm volatile("cp.async.commit_group;");
    }

    for (int kc = 0; kc < 4; ++kc) {
        if (kc < 3) {
            const float* src = W + (kc + 1) * KC * 256;
            float* dst = wbuf + ((kc + 1) & 1) * KC * WSTRIDE;
            #pragma unroll
            for (int it = 0; it < 8; ++it) {
                int idx = it * THREADS + tid;
                int row = idx >> 6, q = idx & 63;
                cp_async16(dst + row * WSTRIDE + q * 4, src + row * 256 + q * 4);
            }
            asm volatile("cp.async.commit_group;");
            asm volatile("cp.async.wait_group 1;");
        } else {
            asm volatile("cp.async.wait_group 0;");
        }
        __syncthreads();

        const float* wb = wbuf + (kc & 1) * KC * WSTRIDE;
        #pragma unroll
        for (int ks = 0; ks < 8; ++ks) {
            const int k = kc * KC + ks * 8;
            uint32_t a[2][4];
            #pragma unroll
            for (int mf = 0; mf < 2; ++mf) {
                const float* ap = hb + (wm * 32 + mf * 16 + g) * 256 + k;
                a[mf][0] = f2tf(ap[tig]);
                a[mf][1] = f2tf(ap[8 * 256 + tig]);
                a[mf][2] = f2tf(ap[tig + 4]);
                a[mf][3] = f2tf(ap[8 * 256 + tig + 4]);
            }
            #pragma unroll
            for (int nt = 0; nt < 8; ++nt) {
                const float* bp = wb + (ks * 8 + tig) * WSTRIDE + wn * 64 + nt * 8 + g;
                uint32_t b0 = f2tf(bp[0]);
                uint32_t b1 = f2tf(bp[4 * WSTRIDE]);
                mma_tf32(acc[0][nt], a[0][0], a[0][1], a[0][2], a[0][3], b0, b1);
                mma_tf32(acc[1][nt], a[1][0], a[1][1], a[1][2], a[1][3], b0, b1);
            }
        }
        __syncthreads();
    }

    // ---------------- Epilogue phase 1: e = exp(tanh(s + bias)); column sums -------
    // scores are tanh(.) in (-1,1): softmax max-subtraction is unnecessary.
    float psum[16];
    #pragma unroll
    for (int j = 0; j < 16; ++j) psum[j] = 0.0f;

    #pragma unroll
    for (int mf = 0; mf < 2; ++mf)
        #pragma unroll
        for (int nt = 0; nt < 8; ++nt)
            #pragma unroll
            for (int i = 0; i < 4; ++i) {
                int row = wm * 32 + mf * 16 + g + ((i >> 1) << 3);
                int col = wn * 64 + nt * 8 + 2 * tig + (i & 1);
                int n = row & 63;
                float s = acc[mf][nt][i] + bias[n * 256 + col];
                float e = __expf(tanhf(s));
                acc[mf][nt][i] = e;
                psum[nt * 2 + (i & 1)] += e;
            }

    // reduce column partials over g (lanes differing in bits 2..4)
    #pragma unroll
    for (int j = 0; j < 16; ++j) {
        psum[j] += __shfl_xor_sync(0xffffffffu, psum[j], 4);
        psum[j] += __shfl_xor_sync(0xffffffffu, psum[j], 8);
        psum[j] += __shfl_xor_sync(0xffffffffu, psum[j], 16);
    }
    if (g == 0) {
        #pragma unroll
        for (int nt = 0; nt < 8; ++nt)
            #pragma unroll
            for (int p = 0; p < 2; ++p) {
                int col = wn * 64 + nt * 8 + 2 * tig + p;
                colpart[(wm & 1) * 512 + batch * 256 + col] = psum[nt * 2 + p];
            }
    }
    __syncthreads();

    if (tid < 512) inv[tid] = 1.0f / (colpart[tid] + colpart[512 + tid]);
    __syncthreads();

    // ---------------- Epilogue phase 2: out[n] = sum_d e * inv[d] * h[n,d] ---------
    float part[4] = {0.0f, 0.0f, 0.0f, 0.0f};
    #pragma unroll
    for (int mf = 0; mf < 2; ++mf)
        #pragma unroll
        for (int nt = 0; nt < 8; ++nt)
            #pragma unroll
            for (int i = 0; i < 4; ++i) {
                int row = wm * 32 + mf * 16 + g + ((i >> 1) << 3);
                int col = wn * 64 + nt * 8 + 2 * tig + (i & 1);
                float e  = acc[mf][nt][i];
                float iv = inv[batch * 256 + col];
                float hv = hb[row * 256 + col];
                part[mf * 2 + (i >> 1)] += e * iv * hv;
            }

    // reduce row partials over tig (lane bits 0..1)
    #pragma unroll
    for (int s = 0; s < 4; ++s) {
        part[s] += __shfl_xor_sync(0xffffffffu, part[s], 1);
        part[s] += __shfl_xor_sync(0xffffffffu, part[s], 2);
    }
    if (tig == 0) {
        #pragma unroll
        for (int s = 0; s < 4; ++s) {
            int row = wm * 32 + (s >> 1) * 16 + g + ((s & 1) << 3);
            rowpart[wn * 128 + row] = part[s];
        }
    }
    __syncthreads();

    if (tid < 128) {
        float v = rowpart[tid] + rowpart[128 + tid] + rowpart[256 + tid] + rowpart[384 + tid];
        out[(size_t)blockIdx.x * 128 + tid] = v;
    }
}

extern "C" void kernel_launch(void* const* d_in, const int* in_sizes, int n_in,
                              void* d_out, int out_size) {
    const float* h    = (const float*)d_in[0];  // [4096, 64, 256]
    const float* W    = (const float*)d_in[1];  // [256, 256]
    const float* bias = (const float*)d_in[2];  // [64, 256]
    float* out = (float*)d_out;                 // [4096, 64]

    const size_t smem_bytes = (size_t)SMEM_FLOATS * sizeof(float);  // ~143 KB
    cudaFuncSetAttribute(aspect_attention_kernel,
                         cudaFuncAttributeMaxDynamicSharedMemorySize, (int)smem_bytes);

    aspect_attention_kernel<<<2048, THREADS, smem_bytes>>>(h, W, bias, out);
}

// round 3
// speedup vs baseline: 2.1482x; 2.1482x over previous
#include <cuda_runtime.h>
#include <cstdint>
#include <cstddef>

// AspectAttention round 3: tf32 mma.sync with smem-staged fragment-friendly operands.
// CTA: 128 rows (2 batches) x 256 cols, 256 threads = 8 warps (2m x 4n), warp tile 64x64.
// K=256 in eight KC=32 chunks, 3-stage cp.async pipeline.
// A (h) staged row-major with pad-36 (conflict-free scalar LDS).
// B (W) pre-packed into per-thread fragment order (conflict-free LDS.64).

#define THREADS   256
#define KC        32
#define APAD      36                      // floats per staged h row
#define SA_STAGE  (128 * APAD)            // 4608 floats
#define SB_STAGE  (4 * 256 * 8)           // 8192 floats (4 k-steps x 256 cols x {4 tig x 2})
#define NSTAGE    3
#define SA_OFF(s) ((s) * SA_STAGE)
#define SB_OFF(s) (NSTAGE * SA_STAGE + (s) * SB_STAGE)
#define ROWPART_OFF (NSTAGE * (SA_STAGE + SB_STAGE))
#define SMEM_FLOATS (ROWPART_OFF + 4 * 128)

__device__ float g_Wpack[32 * 256 * 8];   // [kb][col][tig][{b0,b1}], tf32-rounded

// ---------------- helpers ----------------
__device__ __forceinline__ uint32_t f2tf(float x) {
    uint32_t r; asm("cvt.rna.tf32.f32 %0, %1;" : "=r"(r) : "f"(x)); return r;
}
__device__ __forceinline__ float tanh_fast(float x) {
    float y; asm("tanh.approx.f32 %0, %1;" : "=f"(y) : "f"(x)); return y;
}
__device__ __forceinline__ void mma_tf32(float (&c)[4],
                                         uint32_t a0, uint32_t a1, uint32_t a2, uint32_t a3,
                                         uint32_t b0, uint32_t b1) {
    asm volatile(
        "mma.sync.aligned.m16n8k8.row.col.f32.tf32.tf32.f32 "
        "{%0,%1,%2,%3},{%4,%5,%6,%7},{%8,%9},{%0,%1,%2,%3};"
        : "+f"(c[0]), "+f"(c[1]), "+f"(c[2]), "+f"(c[3])
        : "r"(a0), "r"(a1), "r"(a2), "r"(a3), "r"(b0), "r"(b1));
}
__device__ __forceinline__ void cp_async16(uint32_t sa, const void* g) {
    asm volatile("cp.async.cg.shared.global [%0], [%1], 16;" :: "r"(sa), "l"(g));
}

// ---------------- W pre-pack: Wpack[kb][col][tig][{k=kb*8+tig, k+4}] ----------------
__global__ void pack_w_kernel(const float* __restrict__ W) {
    const int kb  = blockIdx.x;      // 0..31
    const int col = threadIdx.x;     // 0..255
    float2* dst = (float2*)g_Wpack;
    #pragma unroll
    for (int t = 0; t < 4; ++t) {
        float2 v;
        v.x = __uint_as_float(f2tf(W[(kb * 8 + t)     * 256 + col]));
        v.y = __uint_as_float(f2tf(W[(kb * 8 + t + 4) * 256 + col]));
        dst[(kb * 256 + col) * 4 + t] = v;
    }
}

// ---------------- GEMM chunk ----------------
__device__ __forceinline__ void compute_chunk(const float* __restrict__ sA,
                                              const float* __restrict__ sB,
                                              float (&acc)[4][8][4],
                                              int wm, int wn, int g, int tig) {
    #pragma unroll
    for (int ks = 0; ks < 4; ++ks) {
        uint32_t a[4][4];
        #pragma unroll
        for (int mf = 0; mf < 4; ++mf) {
            const float* ap = sA + (wm * 64 + mf * 16 + g) * APAD + ks * 8 + tig;
            a[mf][0] = __float_as_uint(ap[0]);           // (g,      k+tig)
            a[mf][1] = __float_as_uint(ap[8 * APAD]);    // (g+8,    k+tig)
            a[mf][2] = __float_as_uint(ap[4]);           // (g,      k+tig+4)
            a[mf][3] = __float_as_uint(ap[8 * APAD + 4]);
        }
        const float2* bp = (const float2*)sB + (ks * 256 + wn * 64 + g) * 4 + tig;
        #pragma unroll
        for (int nt = 0; nt < 8; ++nt) {
            float2 b = bp[nt * 32];
            uint32_t b0 = __float_as_uint(b.x), b1 = __float_as_uint(b.y);
            #pragma unroll
            for (int mf = 0; mf < 4; ++mf)
                mma_tf32(acc[mf][nt], a[mf][0], a[mf][1], a[mf][2], a[mf][3], b0, b1);
        }
    }
}

// ---------------- main kernel ----------------
__global__ __launch_bounds__(THREADS)
void aspect_attention_kernel(const float* __restrict__ h,
                             const float* __restrict__ bias,
                             float* __restrict__ out) {
    extern __shared__ float smem_f[];
    const uint32_t smem_u32 = (uint32_t)__cvta_generic_to_shared(smem_f);

    const int tid  = threadIdx.x;
    const int w    = tid >> 5;
    const int lane = tid & 31;
    const int g    = lane >> 2;
    const int tig  = lane & 3;
    const int wm   = w & 1;       // row block: wm*64
    const int wn   = w >> 1;      // col block: wn*64

    const float* hb = h + (size_t)blockIdx.x * (128 * 256);

    float acc[4][8][4];
    #pragma unroll
    for (int mf = 0; mf < 4; ++mf)
        #pragma unroll
        for (int nt = 0; nt < 8; ++nt)
            #pragma unroll
            for (int i = 0; i < 4; ++i) acc[mf][nt][i] = 0.0f;

    // ---- cp.async chunk staging ----
    #define ISSUE(c, s) do {                                                      \
        const float* asrc_ = hb + (c) * KC;                                       \
        _Pragma("unroll")                                                         \
        for (int it = 0; it < 4; ++it) {                                          \
            int i_ = it * THREADS + tid;                                          \
            int r_ = i_ >> 3, q_ = i_ & 7;                                        \
            cp_async16(smem_u32 + (SA_OFF(s) + r_ * APAD + q_ * 4) * 4,           \
                       asrc_ + r_ * 256 + q_ * 4);                                \
        }                                                                         \
        const float* bsrc_ = g_Wpack + (c) * SB_STAGE;                            \
        _Pragma("unroll")                                                         \
        for (int it = 0; it < 8; ++it) {                                          \
            int i_ = it * THREADS + tid;                                          \
            cp_async16(smem_u32 + (SB_OFF(s) + i_ * 4) * 4, bsrc_ + i_ * 4);      \
        }                                                                         \
        asm volatile("cp.async.commit_group;");                                   \
    } while (0)

    ISSUE(0, 0); ISSUE(1, 1); ISSUE(2, 2);

    #define STEP(c, waitn) do {                                                   \
        asm volatile("cp.async.wait_group %0;" :: "n"(waitn));                    \
        __syncthreads();                                                          \
        compute_chunk(smem_f + SA_OFF((c) % 3), smem_f + SB_OFF((c) % 3),         \
                      acc, wm, wn, g, tig);                                       \
        if ((c) + 3 < 8) { __syncthreads(); ISSUE((c) + 3, (c) % 3); }            \
    } while (0)

    STEP(0, 2); STEP(1, 2); STEP(2, 2); STEP(3, 2);
    STEP(4, 2); STEP(5, 2); STEP(6, 1); STEP(7, 0);

    // ---- epilogue phase 1: e = exp(tanh(s + bias)); per-warp column sums ----
    // Each warp owns a full 64-row batch slice x 64 cols: colsum is intra-warp.
    float psum[16];
    #pragma unroll
    for (int j = 0; j < 16; ++j) psum[j] = 0.0f;

    #pragma unroll
    for (int mf = 0; mf < 4; ++mf)
        #pragma unroll
        for (int hi = 0; hi < 2; ++hi) {
            int row = wm * 64 + mf * 16 + hi * 8 + g;
            const float* brow = bias + (row & 63) * 256 + wn * 64 + 2 * tig;
            #pragma unroll
            for (int nt = 0; nt < 8; ++nt) {
                float2 bb = *(const float2*)(brow + nt * 8);
                float e0 = __expf(tanh_fast(acc[mf][nt][2 * hi + 0] + bb.x));
                float e1 = __expf(tanh_fast(acc[mf][nt][2 * hi + 1] + bb.y));
                acc[mf][nt][2 * hi + 0] = e0;
                acc[mf][nt][2 * hi + 1] = e1;
                psum[nt * 2 + 0] += e0;
                psum[nt * 2 + 1] += e1;
            }
        }

    // butterfly over g bits (2..4): every lane ends with the full column sum
    #pragma unroll
    for (int j = 0; j < 16; ++j) {
        psum[j] += __shfl_xor_sync(0xffffffffu, psum[j], 4);
        psum[j] += __shfl_xor_sync(0xffffffffu, psum[j], 8);
        psum[j] += __shfl_xor_sync(0xffffffffu, psum[j], 16);
        psum[j] = 1.0f / psum[j];            // psum now holds inv(colsum)
    }

    // ---- phase 2: out[row] = sum_col e * inv * h ----
    float part[8];
    #pragma unroll
    for (int mf = 0; mf < 4; ++mf)
        #pragma unroll
        for (int hi = 0; hi < 2; ++hi) {
            int row = wm * 64 + mf * 16 + hi * 8 + g;
            const float* hrow = hb + row * 256 + wn * 64 + 2 * tig;
            float p = 0.0f;
            #pragma unroll
            for (int nt = 0; nt < 8; ++nt) {
                float2 hh = *(const float2*)(hrow + nt * 8);
                p += acc[mf][nt][2 * hi + 0] * psum[nt * 2 + 0] * hh.x;
                p += acc[mf][nt][2 * hi + 1] * psum[nt * 2 + 1] * hh.y;
            }
            part[mf * 2 + hi] = p;
        }

    // reduce over tig (lane bits 0..1)
    #pragma unroll
    for (int s = 0; s < 8; ++s) {
        part[s] += __shfl_xor_sync(0xffffffffu, part[s], 1);
        part[s] += __shfl_xor_sync(0xffffffffu, part[s], 2);
    }
    float* rowpart = smem_f + ROWPART_OFF;
    if (tig == 0) {
        #pragma unroll
        for (int s = 0; s < 8; ++s) {
            int row = wm * 64 + (s >> 1) * 16 + (s & 1) * 8 + g;
            rowpart[wn * 128 + row] = part[s];
        }
    }
    __syncthreads();

    if (tid < 128) {
        float v = rowpart[tid] + rowpart[128 + tid] + rowpart[256 + tid] + rowpart[384 + tid];
        out[(size_t)blockIdx.x * 128 + tid] = v;
    }
}

extern "C" void kernel_launch(void* const* d_in, const int* in_sizes, int n_in,
                              void* d_out, int out_size) {
    const float* h    = (const float*)d_in[0];  // [4096, 64, 256]
    const float* W    = (const float*)d_in[1];  // [256, 256]
    const float* bias = (const float*)d_in[2];  // [64, 256]
    float* out = (float*)d_out;                 // [4096, 64]

    pack_w_kernel<<<32, 256>>>(W);

    const size_t smem_bytes = (size_t)SMEM_FLOATS * sizeof(float);  // ~152 KB
    cudaFuncSetAttribute(aspect_attention_kernel,
                         cudaFuncAttributeMaxDynamicSharedMemorySize, (int)smem_bytes);
    aspect_attention_kernel<<<2048, THREADS, smem_bytes>>>(h, bias, out);
}

// round 4
// speedup vs baseline: 2.8188x; 1.3122x over previous
#include <cuda_runtime.h>
#include <cuda_fp16.h>
#include <cstdint>
#include <cstddef>

// AspectAttention round 4: fp16 mma.sync m16n8k16 (f32 acc).
// CTA: 128 rows x 256 cols, 256 thr = 8 warps (2m x 4n), warp tile 64x64.
// W pre-packed to fp16 fragment order, fully smem-resident (128KB, loaded once).
// A (h) streamed f32 via cp.async, KC=32 chunks, 4 stages, XOR-swizzled rows,
// converted to fp16 in registers (cvt.rn.f16x2.f32) when building fragments.

#define THREADS   256
#define KC        32
#define ASTAGE    16384                 // 128 rows x 128B (f32, swizzled)
#define AOFF(s)   ((s) * ASTAGE)
#define BOFF      65536                 // 4 stages of A
#define BBYTES    131072                // 16 steps x 256 cols x 4 tig x 8B
#define RP_OFF    (BOFF + BBYTES)       // rowpart: 512 floats
#define SMEM_BYTES (RP_OFF + 2048)

__device__ __half g_Wpack[16 * 256 * 16];   // [s][col][tig][{b0.lo,b0.hi,b1.lo,b1.hi}]

// ---------------- helpers ----------------
__device__ __forceinline__ float tanh_fast(float x) {
    float y; asm("tanh.approx.f32 %0, %1;" : "=f"(y) : "f"(x)); return y;
}
__device__ __forceinline__ uint32_t pack2(float hi, float lo) {
    uint32_t r; asm("cvt.rn.f16x2.f32 %0, %1, %2;" : "=r"(r) : "f"(hi), "f"(lo)); return r;
}
__device__ __forceinline__ void mma_fp16(float (&c)[4],
                                         uint32_t a0, uint32_t a1, uint32_t a2, uint32_t a3,
                                         uint32_t b0, uint32_t b1) {
    asm volatile(
        "mma.sync.aligned.m16n8k16.row.col.f32.f16.f16.f32 "
        "{%0,%1,%2,%3},{%4,%5,%6,%7},{%8,%9},{%0,%1,%2,%3};"
        : "+f"(c[0]), "+f"(c[1]), "+f"(c[2]), "+f"(c[3])
        : "r"(a0), "r"(a1), "r"(a2), "r"(a3), "r"(b0), "r"(b1));
}
__device__ __forceinline__ void cp_async16(uint32_t sa, const void* g) {
    asm volatile("cp.async.cg.shared.global [%0], [%1], 16;" :: "r"(sa), "l"(g));
}

// ---------------- W pack: fp16 fragment order ----------------
// g_Wpack[((s*256 + col)*4 + t)*4 + j] = fp16(W[16s + 2t + (j&1) + (j>>1)*8, col])
__global__ void pack_w_kernel(const float* __restrict__ W) {
    const int s   = blockIdx.x;      // 0..15
    const int col = threadIdx.x;     // 0..255
    #pragma unroll
    for (int t = 0; t < 4; ++t) {
        __half* dst = g_Wpack + ((s * 256 + col) * 4 + t) * 4;
        dst[0] = __float2half_rn(W[(16 * s + 2 * t)     * 256 + col]);
        dst[1] = __float2half_rn(W[(16 * s + 2 * t + 1) * 256 + col]);
        dst[2] = __float2half_rn(W[(16 * s + 2 * t + 8) * 256 + col]);
        dst[3] = __float2half_rn(W[(16 * s + 2 * t + 9) * 256 + col]);
    }
}

// ---------------- main kernel ----------------
__global__ __launch_bounds__(THREADS)
void aspect_attention_kernel(const float* __restrict__ h,
                             const float* __restrict__ bias,
                             float* __restrict__ out) {
    extern __shared__ __align__(16) char dynsmem[];
    const uint32_t smem_u32 = (uint32_t)__cvta_generic_to_shared(dynsmem);

    const int tid  = threadIdx.x;
    const int w    = tid >> 5;
    const int lane = tid & 31;
    const int g    = lane >> 2;
    const int tig  = lane & 3;
    const int wm   = w & 1;       // row block: wm*64
    const int wn   = w >> 1;      // col block: wn*64

    const float* hb = h + (size_t)blockIdx.x * (128 * 256);

    float acc[4][8][4];
    #pragma unroll
    for (int mf = 0; mf < 4; ++mf)
        #pragma unroll
        for (int nt = 0; nt < 8; ++nt)
            #pragma unroll
            for (int i = 0; i < 4; ++i) acc[mf][nt][i] = 0.0f;

    // ---- A chunk issuer: f32 rows, 128B stride, XOR (row&3)<<5 swizzle ----
    #define ISSUE_A(c, slot) do {                                                 \
        _Pragma("unroll")                                                         \
        for (int it = 0; it < 4; ++it) {                                          \
            int i_ = it * THREADS + tid;                                          \
            int r_ = i_ >> 3, q_ = i_ & 7;                                        \
            uint32_t d_ = (uint32_t)(r_ * 128 + q_ * 16) ^ ((uint32_t)(r_ & 3) << 5); \
            cp_async16(smem_u32 + AOFF(slot) + d_, hb + r_ * 256 + (c) * KC + q_ * 4); \
        }                                                                         \
        asm volatile("cp.async.commit_group;");                                   \
    } while (0)

    // prologue: B (whole W pack, once) + A0 in group 0; A1, A2 in groups 1,2
    {
        const char* bsrc = (const char*)g_Wpack;
        #pragma unroll
        for (int it = 0; it < 32; ++it) {
            int i_ = it * THREADS + tid;
            cp_async16(smem_u32 + BOFF + i_ * 16, bsrc + i_ * 16);
        }
        #pragma unroll
        for (int it = 0; it < 4; ++it) {
            int i_ = it * THREADS + tid;
            int r_ = i_ >> 3, q_ = i_ & 7;
            uint32_t d_ = (uint32_t)(r_ * 128 + q_ * 16) ^ ((uint32_t)(r_ & 3) << 5);
            cp_async16(smem_u32 + AOFF(0) + d_, hb + r_ * 256 + q_ * 4);
        }
        asm volatile("cp.async.commit_group;");
    }
    ISSUE_A(1, 1);
    ISSUE_A(2, 2);

    const char* sB = dynsmem + BOFF;

    #define STEP(c, waitn) do {                                                   \
        asm volatile("cp.async.wait_group %0;" :: "n"(waitn));                    \
        __syncthreads();                                                          \
        if ((c) + 3 < 8) ISSUE_A((c) + 3, ((c) + 3) & 3);                         \
        const char* sA = dynsmem + AOFF((c) & 3);                                 \
        _Pragma("unroll")                                                         \
        for (int ss = 0; ss < 2; ++ss) {                                          \
            uint32_t a[4][4];                                                     \
            _Pragma("unroll")                                                     \
            for (int mf = 0; mf < 4; ++mf) {                                      \
                int row = wm * 64 + mf * 16 + g;                                  \
                uint32_t X = (uint32_t)(row & 3) << 5;                            \
                uint32_t x0 = ((uint32_t)(row * 128 + (ss * 16 + 2 * tig) * 4)) ^ X; \
                uint32_t x2 = ((uint32_t)(row * 128 + (ss * 16 + 8 + 2 * tig) * 4)) ^ X; \
                float2 v0 = *(const float2*)(sA + x0);                            \
                float2 v1 = *(const float2*)(sA + x0 + 1024);                     \
                float2 v2 = *(const float2*)(sA + x2);                            \
                float2 v3 = *(const float2*)(sA + x2 + 1024);                     \
                a[mf][0] = pack2(v0.y, v0.x);                                     \
                a[mf][1] = pack2(v1.y, v1.x);                                     \
                a[mf][2] = pack2(v2.y, v2.x);                                     \
                a[mf][3] = pack2(v3.y, v3.x);                                     \
            }                                                                     \
            const int sg = (c) * 2 + ss;                                          \
            _Pragma("unroll")                                                     \
            for (int nt = 0; nt < 8; ++nt) {                                      \
                int col = wn * 64 + nt * 8 + g;                                   \
                uint2 bb = *(const uint2*)(sB + ((sg * 256 + col) * 4 + tig) * 8);\
                _Pragma("unroll")                                                 \
                for (int mf = 0; mf < 4; ++mf)                                    \
                    mma_fp16(acc[mf][nt], a[mf][0], a[mf][1], a[mf][2], a[mf][3], \
                             bb.x, bb.y);                                         \
            }                                                                     \
        }                                                                         \
    } while (0)

    STEP(0, 2); STEP(1, 2); STEP(2, 2); STEP(3, 2);
    STEP(4, 2); STEP(5, 2); STEP(6, 1); STEP(7, 0);

    // ---- epilogue phase 1: e = exp(tanh(s + bias)); intra-warp column sums ----
    float psum[16];
    #pragma unroll
    for (int j = 0; j < 16; ++j) psum[j] = 0.0f;

    #pragma unroll
    for (int mf = 0; mf < 4; ++mf)
        #pragma unroll
        for (int hi = 0; hi < 2; ++hi) {
            int row = wm * 64 + mf * 16 + hi * 8 + g;
            const float* brow = bias + (row & 63) * 256 + wn * 64 + 2 * tig;
            #pragma unroll
            for (int nt = 0; nt < 8; ++nt) {
                float2 bb = *(const float2*)(brow + nt * 8);
                float e0 = __expf(tanh_fast(acc[mf][nt][2 * hi + 0] + bb.x));
                float e1 = __expf(tanh_fast(acc[mf][nt][2 * hi + 1] + bb.y));
                acc[mf][nt][2 * hi + 0] = e0;
                acc[mf][nt][2 * hi + 1] = e1;
                psum[nt * 2 + 0] += e0;
                psum[nt * 2 + 1] += e1;
            }
        }

    #pragma unroll
    for (int j = 0; j < 16; ++j) {
        psum[j] += __shfl_xor_sync(0xffffffffu, psum[j], 4);
        psum[j] += __shfl_xor_sync(0xffffffffu, psum[j], 8);
        psum[j] += __shfl_xor_sync(0xffffffffu, psum[j], 16);
        psum[j] = 1.0f / psum[j];            // inv(colsum)
    }

    // ---- phase 2: out[row] = sum_col e * inv * h ----
    float part[8];
    #pragma unroll
    for (int mf = 0; mf < 4; ++mf)
        #pragma unroll
        for (int hi = 0; hi < 2; ++hi) {
            int row = wm * 64 + mf * 16 + hi * 8 + g;
            const float* hrow = hb + row * 256 + wn * 64 + 2 * tig;
            float p = 0.0f;
            #pragma unroll
            for (int nt = 0; nt < 8; ++nt) {
                float2 hh = *(const float2*)(hrow + nt * 8);
                p += acc[mf][nt][2 * hi + 0] * psum[nt * 2 + 0] * hh.x;
                p += acc[mf][nt][2 * hi + 1] * psum[nt * 2 + 1] * hh.y;
            }
            part[mf * 2 + hi] = p;
        }

    #pragma unroll
    for (int s = 0; s < 8; ++s) {
        part[s] += __shfl_xor_sync(0xffffffffu, part[s], 1);
        part[s] += __shfl_xor_sync(0xffffffffu, part[s], 2);
    }
    float* rowpart = (float*)(dynsmem + RP_OFF);
    __syncthreads();   // A stages no longer needed; rowpart region is distinct anyway
    if (tig == 0) {
        #pragma unroll
        for (int s = 0; s < 8; ++s) {
            int row = wm * 64 + (s >> 1) * 16 + (s & 1) * 8 + g;
            rowpart[wn * 128 + row] = part[s];
        }
    }
    __syncthreads();

    if (tid < 128) {
        float v = rowpart[tid] + rowpart[128 + tid] + rowpart[256 + tid] + rowpart[384 + tid];
        out[(size_t)blockIdx.x * 128 + tid] = v;
    }
}

extern "C" void kernel_launch(void* const* d_in, const int* in_sizes, int n_in,
                              void* d_out, int out_size) {
    const float* h    = (const float*)d_in[0];  // [4096, 64, 256]
    const float* W    = (const float*)d_in[1];  // [256, 256]
    const float* bias = (const float*)d_in[2];  // [64, 256]
    float* out = (float*)d_out;                 // [4096, 64]

    pack_w_kernel<<<16, 256>>>(W);

    cudaFuncSetAttribute(aspect_attention_kernel,
                         cudaFuncAttributeMaxDynamicSharedMemorySize, SMEM_BYTES);
    aspect_attention_kernel<<<2048, THREADS, SMEM_BYTES>>>(h, bias, out);
}